// round 4
// baseline (speedup 1.0000x reference)
#include <cuda_runtime.h>
#include <cuda_bf16.h>
#include <cstdint>

// Problem constants
#define BATCH 32
#define CIN   64
#define HH    56
#define WW    56
#define NOUT  128
#define IMG   (HH*WW)          // 3136

// Tiling
#define MTILE 224              // 4 output rows x 56 cols
#define ROWS_PER_CTA 4
#define IN_LINES (6*58)        // halo tile lines (6 rows x 58 cols)
#define IN_SM_BYTES (IN_LINES*128)     // 44544 bytes (64 ch * 2B, swizzled per line)
#define WROW 72                // padded channels per weight row (144B stride)
#define WKK_BYTES (128*WROW*2) // 18432 bytes per (kh,kw)
#define SMEM_TOTAL (IN_SM_BYTES + 9*WKK_BYTES)   // 44544 + 165888 = 210432

// Pre-quantized weights: [kk(9)][n(128)][c(64)] bf16
__device__ __nv_bfloat16 g_wq[9*128*64];

__global__ void wprep_kernel(const float* __restrict__ w) {
    int idx = blockIdx.x * 256 + threadIdx.x;
    if (idx >= 9*128*64) return;
    int kk  = idx / (128*64);
    int rem = idx - kk*(128*64);
    int n   = rem >> 6;
    int c   = rem & 63;
    // gmem weight layout [n][c][kh][kw]
    g_wq[idx] = __float2bfloat16(w[(n*64 + c)*9 + kk]);   // RNE == float_quantize(8,7)
}

__global__ void __launch_bounds__(256, 1)
conv_kernel(const float* __restrict__ in, const float* __restrict__ bias,
            float* __restrict__ out) {
    extern __shared__ __nv_bfloat16 sm[];
    char* insmB = (char*)sm;
    char* wsmB  = (char*)sm + IN_SM_BYTES;

    const int ty   = blockIdx.x;     // 0..13  (group of 4 output rows)
    const int b    = blockIdx.y;     // 0..31
    const int tid  = threadIdx.x;
    const int lane = tid & 31;
    const int warp = tid >> 5;
    const int y0   = ty * ROWS_PER_CTA;

    // ---------------- stage all weights (bf16, coalesced 16B) ----------------
    {
        const uint4* wqv = (const uint4*)g_wq;           // 9216 uint4 total
        #pragma unroll 4
        for (int it = 0; it < 36; ++it) {
            int s = it*256 + tid;
            uint4 v = wqv[s];
            int row = s >> 3;      // kk*128 + n
            int col = s & 7;       // 8-bf16 chunk within the 64-ch row
            *(uint4*)(wsmB + row*144 + col*16) = v;
        }
    }

    // ---------------- stage input halo tile (fp32 -> bf16, swizzled) ---------
    {
        const float* inb = in + (size_t)b * CIN * IMG;
        #pragma unroll 4
        for (int it = 0; it < 96; ++it) {
            int s  = it*256 + tid;      // 0..24575
            int r  = s >> 12;           // 0..5   (tile row, = y - (y0-1))
            int c  = (s >> 6) & 63;     // channel
            int xi = s & 63;            // tile col (x = xi-1), 58..63 unused
            int y  = y0 - 1 + r;
            int x  = xi - 1;
            float v = 0.f;
            if (y >= 0 && y < HH && x >= 0 && x < WW)
                v = inb[c*IMG + y*WW + x];
            if (xi < 58) {
                int line = r*58 + xi;
                int byte = line*128 + ((((c >> 3) ^ (line & 7)) << 4) | ((c & 7)*2));
                *(__nv_bfloat16*)(insmB + byte) = __float2bfloat16(v);
            }
        }
    }
    __syncthreads();

    // ---------------- warp tiling: 2(M) x 4(N) warps ----------------
    const int warpM = warp & 1;        // 0..1 -> 112 pixels each
    const int warpN = warp >> 1;       // 0..3 -> 32 channels each
    const int g  = lane >> 2;          // group id 0..7
    const int kq = lane & 3;           // 0..3

    // line base (pixel -> halo-tile line) for the 14 m-rows this thread touches
    int lineBase[14];
    #pragma unroll
    for (int mi = 0; mi < 7; ++mi) {
        int p0 = warpM*112 + mi*16 + g;
        int p1 = p0 + 8;
        lineBase[mi*2]     = (p0/56)*58 + (p0 % 56);
        lineBase[mi*2 + 1] = (p1/56)*58 + (p1 % 56);
    }

    float acc[7][4][4];
    #pragma unroll
    for (int mi = 0; mi < 7; ++mi)
        #pragma unroll
        for (int ni = 0; ni < 4; ++ni)
            #pragma unroll
            for (int q = 0; q < 4; ++q) acc[mi][ni][q] = 0.f;

    // ---------------- main loop: 9 (kh,kw) x 4 k16-steps over 64 channels ----
    int kh = 0, kw = 0;
    #pragma unroll 1
    for (int kk = 0; kk < 9; ++kk) {
        const int lineOff = kh*58 + kw;
        const char* wkk = wsmB + kk * WKK_BYTES;

        #pragma unroll
        for (int ks = 0; ks < 4; ++ks) {
            // B fragments: W[n][k] row-major -> {b0,b1} straight 32-bit loads
            uint32_t bb[4][2];
            const int krow = ks*16 + kq*2;
            #pragma unroll
            for (int ni = 0; ni < 4; ++ni) {
                int n = warpN*32 + ni*8 + g;
                const char* bp = wkk + n*144 + krow*2;
                bb[ni][0] = *(const uint32_t*)bp;          // k, k+1
                bb[ni][1] = *(const uint32_t*)(bp + 16);   // k+8, k+9
            }
            const int c0 = ks*2;   // 8-ch chunk index of k-lo half
            #pragma unroll
            for (int mi = 0; mi < 7; ++mi) {
                int l0 = lineBase[mi*2]     + lineOff;
                int l1 = lineBase[mi*2 + 1] + lineOff;
                uint32_t a0 = *(const uint32_t*)(insmB + l0*128 + ((( c0    ^ (l0&7))<<4) | (kq*4)));
                uint32_t a1 = *(const uint32_t*)(insmB + l1*128 + ((( c0    ^ (l1&7))<<4) | (kq*4)));
                uint32_t a2 = *(const uint32_t*)(insmB + l0*128 + ((((c0+1) ^ (l0&7))<<4) | (kq*4)));
                uint32_t a3 = *(const uint32_t*)(insmB + l1*128 + ((((c0+1) ^ (l1&7))<<4) | (kq*4)));
                #pragma unroll
                for (int ni = 0; ni < 4; ++ni) {
                    asm volatile(
                        "mma.sync.aligned.m16n8k16.row.col.f32.bf16.bf16.f32 "
                        "{%0,%1,%2,%3}, {%4,%5,%6,%7}, {%8,%9}, {%0,%1,%2,%3};\n"
                        : "+f"(acc[mi][ni][0]), "+f"(acc[mi][ni][1]),
                          "+f"(acc[mi][ni][2]), "+f"(acc[mi][ni][3])
                        : "r"(a0), "r"(a1), "r"(a2), "r"(a3),
                          "r"(bb[ni][0]), "r"(bb[ni][1]));
                }
            }
        }
        if (++kw == 3) { kw = 0; ++kh; }
    }

    // ---------------- epilogue: + bf16(bias), NCHW store ----------------
    float* outb = out + (size_t)b * NOUT * IMG + ty * MTILE;
    #pragma unroll
    for (int ni = 0; ni < 4; ++ni) {
        int n0 = warpN*32 + ni*8 + kq*2;
        float bq0 = __bfloat162float(__float2bfloat16(__ldg(bias + n0)));
        float bq1 = __bfloat162float(__float2bfloat16(__ldg(bias + n0 + 1)));
        float* o0 = outb + n0*IMG;
        float* o1 = o0 + IMG;
        #pragma unroll
        for (int mi = 0; mi < 7; ++mi) {
            int p0 = warpM*112 + mi*16 + g;
            o0[p0]     = acc[mi][ni][0] + bq0;
            o1[p0]     = acc[mi][ni][1] + bq1;
            o0[p0 + 8] = acc[mi][ni][2] + bq0;
            o1[p0 + 8] = acc[mi][ni][3] + bq1;
        }
    }
}

extern "C" void kernel_launch(void* const* d_in, const int* in_sizes, int n_in,
                              void* d_out, int out_size) {
    const float* in   = (const float*)d_in[0];
    const float* w    = (const float*)d_in[1];
    const float* bias = (const float*)d_in[2];
    float* out = (float*)d_out;

    cudaFuncSetAttribute(conv_kernel,
                         cudaFuncAttributeMaxDynamicSharedMemorySize, SMEM_TOTAL);

    wprep_kernel<<<(9*128*64 + 255)/256, 256>>>(w);
    conv_kernel<<<dim3(14, BATCH), 256, SMEM_TOTAL>>>(in, bias, out);
}

// round 5
// speedup vs baseline: 1.4762x; 1.4762x over previous
#include <cuda_runtime.h>
#include <cuda_bf16.h>
#include <cstdint>

// Problem constants
#define BATCH 32
#define CIN   64
#define HH    56
#define WW    56
#define NOUT  128
#define IMG   (HH*WW)          // 3136

// Tiling
#define MTILE 224              // 4 output rows x 56 cols
#define ROWS_PER_CTA 4
#define THREADS 512
#define IN_LINES (6*58)                 // halo tile lines
#define IN_SM_BYTES (IN_LINES*128)      // 44544 (64ch * 2B per line, 8x16B swizzled chunks)
#define WFRAG_U32 (9*4*16*32*2)         // 36864 u32 = 147456 B
#define WFRAG_BYTES (WFRAG_U32*4)
#define SMEM_TOTAL (IN_SM_BYTES + WFRAG_BYTES)   // 192000

// Weights pre-packed in mma B-fragment order: [kk][ks][nb(16)][lane(32)][2] u32
// lane (g=lane>>2, kq=lane&3): u32[0] = W[nb*8+g][ks*16+kq*2 .. +1]
//                              u32[1] = W[nb*8+g][ks*16+8+kq*2 .. +1]
__device__ uint32_t g_wq[WFRAG_U32];

__global__ void wprep_kernel(const float* __restrict__ w) {
    int idx = blockIdx.x * 256 + threadIdx.x;
    if (idx >= WFRAG_U32) return;
    int j    = idx & 1;
    int lane = (idx >> 1) & 31;
    int nb   = (idx >> 6) & 15;
    int ks   = (idx >> 10) & 3;
    int kk   = idx >> 12;
    int g = lane >> 2, kq = lane & 3;
    int n = nb * 8 + g;
    int c = ks * 16 + j * 8 + kq * 2;
    // gmem weight layout [n][c][kh][kw]; RNE fp32->bf16 == float_quantize(8,7)
    __nv_bfloat16 lo = __float2bfloat16(w[(n * 64 + c) * 9 + kk]);
    __nv_bfloat16 hi = __float2bfloat16(w[(n * 64 + c + 1) * 9 + kk]);
    uint32_t v = (uint32_t)(*(const uint16_t*)&lo) |
                 ((uint32_t)(*(const uint16_t*)&hi) << 16);
    g_wq[idx] = v;
}

__global__ void __launch_bounds__(THREADS, 1)
conv_kernel(const float* __restrict__ in, const float* __restrict__ bias,
            float* __restrict__ out) {
    extern __shared__ char smb[];
    char* insmB = smb;
    char* wsmB  = smb + IN_SM_BYTES;

    const int ty   = blockIdx.x;     // 0..13  (group of 4 output rows)
    const int b    = blockIdx.y;     // 0..31
    const int tid  = threadIdx.x;
    const int lane = tid & 31;
    const int warp = tid >> 5;       // 0..15
    const int y0   = ty * ROWS_PER_CTA;

    // ---------------- stage weight fragments (identity copy, 16B coalesced) --
    {
        const uint4* src = (const uint4*)g_wq;     // 9216 uint4
        uint4* dst = (uint4*)wsmB;
        #pragma unroll 6
        for (int it = 0; it < 18; ++it) {
            int s = it * THREADS + tid;
            dst[s] = src[s];
        }
    }

    // ---------------- stage input halo tile (fp32 -> bf16, swizzled) ---------
    {
        const float* inb = in + (size_t)b * CIN * IMG;
        #pragma unroll 4
        for (int it = 0; it < 48; ++it) {
            int s  = it * THREADS + tid;   // 0..24575
            int r  = s >> 12;              // 0..5   (halo row, y = y0-1+r)
            int c  = (s >> 6) & 63;        // channel
            int xi = s & 63;               // halo col (x = xi-1), 58..63 unused
            int y  = y0 - 1 + r;
            int x  = xi - 1;
            float v = 0.f;
            if (y >= 0 && y < HH && x >= 0 && x < WW)
                v = inb[c * IMG + y * WW + x];
            if (xi < 58) {
                int line = r * 58 + xi;
                int byte = line * 128 + ((((c >> 3) ^ (line & 7)) << 4) | ((c & 7) * 2));
                *(__nv_bfloat16*)(insmB + byte) = __float2bfloat16(v);
            }
        }
    }
    __syncthreads();

    // ---------------- warp tiling: 2(M) x 8(N) warps ----------------
    const int warpM = warp & 1;        // 0..1 -> 112 pixels each
    const int warpN = warp >> 1;       // 0..7 -> 16 channels each
    const int g  = lane >> 2;          // 0..7
    const int kq = lane & 3;           // 0..3
    const int rl = lane & 15;          // ldmatrix row within 16-row A tile
    const int hi16 = ((lane >> 4) & 1) << 4;   // k-half select for ldmatrix ptr

    const uint32_t insm32 = (uint32_t)__cvta_generic_to_shared(insmB);
    const uint32_t* wfr = (const uint32_t*)wsmB;

    // per-lane halo-line base for each of the 7 m16 tiles
    int lineBase[7];
    #pragma unroll
    for (int mi = 0; mi < 7; ++mi) {
        int p = warpM * 112 + mi * 16 + rl;
        lineBase[mi] = (p / 56) * 58 + (p % 56);
    }

    float acc[7][2][4];
    #pragma unroll
    for (int mi = 0; mi < 7; ++mi)
        #pragma unroll
        for (int ni = 0; ni < 2; ++ni)
            #pragma unroll
            for (int q = 0; q < 4; ++q) acc[mi][ni][q] = 0.f;

    // ---------------- main loop: 9 (kh,kw) x 4 k16-steps --------------------
    int kh = 0, kw = 0;
    #pragma unroll 1
    for (int kk = 0; kk < 9; ++kk) {
        const int lineOff = kh * 58 + kw;

        uint32_t Q[7], X7[7];
        #pragma unroll
        for (int mi = 0; mi < 7; ++mi) {
            int l = lineBase[mi] + lineOff;
            Q[mi]  = insm32 + l * 128 + hi16;   // fold k-half bit into base
            X7[mi] = (l & 7) << 4;
        }

        #pragma unroll
        for (int ks = 0; ks < 4; ++ks) {
            // B fragments: one LDS.64 per n-tile (conflict-free)
            const uint32_t* bp = wfr + ((((kk * 4 + ks) * 16 + warpN * 2) * 32 + lane) << 1);
            uint2 B0 = *(const uint2*)bp;          // ni = 0
            uint2 B1 = *(const uint2*)(bp + 64);   // ni = 1 (+1 n-block)

            const uint32_t ksel = (uint32_t)(ks * 32);   // chunk*16, hi16 already in Q
            #pragma unroll
            for (int mi = 0; mi < 7; ++mi) {
                uint32_t addr = Q[mi] + (ksel ^ X7[mi]);
                // NOTE: ksel^X7 then +hi16 ok since hi16 bit (4) is disjoint from
                // ksel bits (5..6) and X7 bits (4..6)? hi16 and X7 share bit 4 —
                // must XOR hi16 too. Recompute exactly:
                addr = insm32 + (lineBase[mi] + lineOff) * 128
                     + (((ksel + hi16) ^ X7[mi]));
                uint32_t a0, a1, a2, a3;
                asm volatile(
                    "ldmatrix.sync.aligned.m8n8.x4.shared.b16 {%0,%1,%2,%3}, [%4];\n"
                    : "=r"(a0), "=r"(a1), "=r"(a2), "=r"(a3) : "r"(addr));
                asm volatile(
                    "mma.sync.aligned.m16n8k16.row.col.f32.bf16.bf16.f32 "
                    "{%0,%1,%2,%3}, {%4,%5,%6,%7}, {%8,%9}, {%0,%1,%2,%3};\n"
                    : "+f"(acc[mi][0][0]), "+f"(acc[mi][0][1]),
                      "+f"(acc[mi][0][2]), "+f"(acc[mi][0][3])
                    : "r"(a0), "r"(a1), "r"(a2), "r"(a3),
                      "r"(B0.x), "r"(B0.y));
                asm volatile(
                    "mma.sync.aligned.m16n8k16.row.col.f32.bf16.bf16.f32 "
                    "{%0,%1,%2,%3}, {%4,%5,%6,%7}, {%8,%9}, {%0,%1,%2,%3};\n"
                    : "+f"(acc[mi][1][0]), "+f"(acc[mi][1][1]),
                      "+f"(acc[mi][1][2]), "+f"(acc[mi][1][3])
                    : "r"(a0), "r"(a1), "r"(a2), "r"(a3),
                      "r"(B1.x), "r"(B1.y));
            }
        }
        if (++kw == 3) { kw = 0; ++kh; }
    }

    // ---------------- epilogue: + bf16(bias), NCHW store ----------------
    float* outb = out + (size_t)b * NOUT * IMG + ty * MTILE;
    #pragma unroll
    for (int ni = 0; ni < 2; ++ni) {
        int n0 = warpN * 16 + ni * 8 + kq * 2;
        float bq0 = __bfloat162float(__float2bfloat16(__ldg(bias + n0)));
        float bq1 = __bfloat162float(__float2bfloat16(__ldg(bias + n0 + 1)));
        float* o0 = outb + (size_t)n0 * IMG;
        float* o1 = o0 + IMG;
        #pragma unroll
        for (int mi = 0; mi < 7; ++mi) {
            int p0 = warpM * 112 + mi * 16 + g;
            o0[p0]     = acc[mi][ni][0] + bq0;
            o1[p0]     = acc[mi][ni][1] + bq1;
            o0[p0 + 8] = acc[mi][ni][2] + bq0;
            o1[p0 + 8] = acc[mi][ni][3] + bq1;
        }
    }
}

extern "C" void kernel_launch(void* const* d_in, const int* in_sizes, int n_in,
                              void* d_out, int out_size) {
    const float* in   = (const float*)d_in[0];
    const float* w    = (const float*)d_in[1];
    const float* bias = (const float*)d_in[2];
    float* out = (float*)d_out;

    cudaFuncSetAttribute(conv_kernel,
                         cudaFuncAttributeMaxDynamicSharedMemorySize, SMEM_TOTAL);

    wprep_kernel<<<(WFRAG_U32 + 255) / 256, 256>>>(w);
    conv_kernel<<<dim3(14, BATCH), THREADS, SMEM_TOTAL>>>(in, bias, out);
}

// round 6
// speedup vs baseline: 1.5484x; 1.0489x over previous
#include <cuda_runtime.h>
#include <cuda_bf16.h>
#include <cstdint>

// Problem constants
#define BATCH 32
#define CIN   64
#define HH    56
#define WW    56
#define NOUT  128
#define IMG   (HH*WW)          // 3136

// Tiling
#define MTILE 224              // 4 output rows x 56 cols
#define ROWS_PER_CTA 4
#define THREADS 512
#define IN_LINES (6*58)                 // halo tile lines
#define IN_SM_BYTES (IN_LINES*128)      // 44544 (64ch * 2B per line, 8x16B swizzled chunks)
#define WFRAG_U32 (9*4*8*32*4)          // 36864 u32 = 147456 B
#define WFRAG_BYTES (WFRAG_U32*4)
#define SMEM_TOTAL (IN_SM_BYTES + WFRAG_BYTES)   // 192000

// Weights pre-packed in mma B-fragment order, both n-tiles contiguous per lane:
// [kk][ks][np(8)][lane(32)][4] u32
//   j=0,1 -> n-block nb=np*2   : { W[nb*8+g][ks*16+kq*2], W[..][ks*16+8+kq*2] }
//   j=2,3 -> n-block nb=np*2+1 : same for the next 8 output channels
__device__ uint32_t g_wq[WFRAG_U32];

__global__ void wprep_kernel(const float* __restrict__ w) {
    int idx = blockIdx.x * 256 + threadIdx.x;
    if (idx >= WFRAG_U32) return;
    int j    = idx & 3;
    int lane = (idx >> 2) & 31;
    int np   = (idx >> 7) & 7;
    int ks   = (idx >> 10) & 3;
    int kk   = idx >> 12;
    int g = lane >> 2, kq = lane & 3;
    int nb = np * 2 + (j >> 1);
    int jj = j & 1;
    int n = nb * 8 + g;
    int c = ks * 16 + jj * 8 + kq * 2;
    // gmem weight layout [n][c][kh][kw]; RNE fp32->bf16 == float_quantize(8,7)
    __nv_bfloat16 lo = __float2bfloat16(w[(n * 64 + c) * 9 + kk]);
    __nv_bfloat16 hi = __float2bfloat16(w[(n * 64 + c + 1) * 9 + kk]);
    g_wq[idx] = (uint32_t)(*(const uint16_t*)&lo) |
                ((uint32_t)(*(const uint16_t*)&hi) << 16);
}

__global__ void __launch_bounds__(THREADS, 1)
conv_kernel(const float* __restrict__ in, const float* __restrict__ bias,
            float* __restrict__ out) {
    extern __shared__ char smb[];
    char* insmB = smb;
    char* wsmB  = smb + IN_SM_BYTES;

    const int ty   = blockIdx.x;     // 0..13  (group of 4 output rows)
    const int b    = blockIdx.y;     // 0..31
    const int tid  = threadIdx.x;
    const int lane = tid & 31;
    const int warp = tid >> 5;       // 0..15
    const int y0   = ty * ROWS_PER_CTA;

    // ---- weight fragments: async copy gmem->smem, overlapped with input stage
    {
        uint32_t wdst = (uint32_t)__cvta_generic_to_shared(wsmB);
        const char* wsrc = (const char*)g_wq;
        #pragma unroll 6
        for (int it = 0; it < 18; ++it) {
            int s = it * THREADS + tid;          // 9216 16B chunks
            asm volatile("cp.async.cg.shared.global [%0], [%1], 16;\n"
                         :: "r"(wdst + s * 16), "l"(wsrc + (size_t)s * 16));
        }
        asm volatile("cp.async.commit_group;\n");
    }

    // ---- stage input halo tile (fp32 -> bf16, swizzled) ---------------------
    {
        const float* inb = in + (size_t)b * CIN * IMG;
        #pragma unroll 4
        for (int it = 0; it < 48; ++it) {
            int s  = it * THREADS + tid;   // 0..24575
            int r  = s >> 12;              // 0..5   (halo row, y = y0-1+r)
            int c  = (s >> 6) & 63;        // channel
            int xi = s & 63;               // halo col (x = xi-1), 58..63 unused
            int y  = y0 - 1 + r;
            int x  = xi - 1;
            float v = 0.f;
            if (y >= 0 && y < HH && x >= 0 && x < WW)
                v = inb[c * IMG + y * WW + x];
            if (xi < 58) {
                int line = r * 58 + xi;
                int byte = line * 128 + ((((c >> 3) ^ (line & 7)) << 4) | ((c & 7) * 2));
                *(__nv_bfloat16*)(insmB + byte) = __float2bfloat16(v);
            }
        }
    }
    asm volatile("cp.async.wait_group 0;\n" ::: "memory");
    __syncthreads();

    // ---- warp tiling: 2(M) x 8(N) warps ------------------------------------
    const int warpM = warp & 1;        // 0..1 -> 112 pixels each
    const int warpN = warp >> 1;       // 0..7 -> 16 channels each
    const int g  = lane >> 2;          // 0..7
    const int kq = lane & 3;           // 0..3
    const int rl = lane & 15;          // ldmatrix row within 16-row A tile
    const int hi16 = ((lane >> 4) & 1) << 4;   // k-half select for ldmatrix ptr

    const uint32_t insm32 = (uint32_t)__cvta_generic_to_shared(insmB);
    const uint32_t* wfr = (const uint32_t*)wsmB;

    // per-lane halo-line base for each of the 7 m16 tiles
    int lineBase[7];
    #pragma unroll
    for (int mi = 0; mi < 7; ++mi) {
        int p = warpM * 112 + mi * 16 + rl;
        lineBase[mi] = (p / 56) * 58 + (p % 56);
    }

    float acc[7][2][4];
    #pragma unroll
    for (int mi = 0; mi < 7; ++mi)
        #pragma unroll
        for (int ni = 0; ni < 2; ++ni)
            #pragma unroll
            for (int q = 0; q < 4; ++q) acc[mi][ni][q] = 0.f;

    // ---- main loop: 9 (kh,kw) x 4 k16-steps --------------------------------
    int kh = 0, kw = 0;
    #pragma unroll 1
    for (int kk = 0; kk < 9; ++kk) {
        const int lineOff = kh * 58 + kw;

        uint32_t base[7], X7[7];
        #pragma unroll
        for (int mi = 0; mi < 7; ++mi) {
            int l = lineBase[mi] + lineOff;
            base[mi] = insm32 + l * 128;
            X7[mi]   = (l & 7) << 4;
        }

        #pragma unroll
        for (int ks = 0; ks < 4; ++ks) {
            // B fragments: single conflict-free LDS.128 covers both n-tiles
            uint4 B = *(const uint4*)(wfr + ((((kk * 4 + ks) * 8 + warpN) * 32 + lane) << 2));

            // batch 1: all 7 ldmatrix.x4 (A fragments for this k16-step)
            const uint32_t off = (uint32_t)(ks * 32 + hi16);
            uint32_t a[7][4];
            #pragma unroll
            for (int mi = 0; mi < 7; ++mi) {
                uint32_t addr = base[mi] + (off ^ X7[mi]);
                asm volatile(
                    "ldmatrix.sync.aligned.m8n8.x4.shared.b16 {%0,%1,%2,%3}, [%4];\n"
                    : "=r"(a[mi][0]), "=r"(a[mi][1]), "=r"(a[mi][2]), "=r"(a[mi][3])
                    : "r"(addr));
            }

            // batch 2: all 14 mma (LDSM latency hidden behind the issue burst)
            #pragma unroll
            for (int mi = 0; mi < 7; ++mi) {
                asm volatile(
                    "mma.sync.aligned.m16n8k16.row.col.f32.bf16.bf16.f32 "
                    "{%0,%1,%2,%3}, {%4,%5,%6,%7}, {%8,%9}, {%0,%1,%2,%3};\n"
                    : "+f"(acc[mi][0][0]), "+f"(acc[mi][0][1]),
                      "+f"(acc[mi][0][2]), "+f"(acc[mi][0][3])
                    : "r"(a[mi][0]), "r"(a[mi][1]), "r"(a[mi][2]), "r"(a[mi][3]),
                      "r"(B.x), "r"(B.y));
                asm volatile(
                    "mma.sync.aligned.m16n8k16.row.col.f32.bf16.bf16.f32 "
                    "{%0,%1,%2,%3}, {%4,%5,%6,%7}, {%8,%9}, {%0,%1,%2,%3};\n"
                    : "+f"(acc[mi][1][0]), "+f"(acc[mi][1][1]),
                      "+f"(acc[mi][1][2]), "+f"(acc[mi][1][3])
                    : "r"(a[mi][0]), "r"(a[mi][1]), "r"(a[mi][2]), "r"(a[mi][3]),
                      "r"(B.z), "r"(B.w));
            }
        }
        if (++kw == 3) { kw = 0; ++kh; }
    }

    // ---- epilogue: + bf16(bias), NCHW store --------------------------------
    float* outb = out + (size_t)b * NOUT * IMG + ty * MTILE;
    #pragma unroll
    for (int ni = 0; ni < 2; ++ni) {
        int n0 = warpN * 16 + ni * 8 + kq * 2;
        float bq0 = __bfloat162float(__float2bfloat16(__ldg(bias + n0)));
        float bq1 = __bfloat162float(__float2bfloat16(__ldg(bias + n0 + 1)));
        float* o0 = outb + (size_t)n0 * IMG;
        float* o1 = o0 + IMG;
        #pragma unroll
        for (int mi = 0; mi < 7; ++mi) {
            int p0 = warpM * 112 + mi * 16 + g;
            o0[p0]     = acc[mi][ni][0] + bq0;
            o1[p0]     = acc[mi][ni][1] + bq1;
            o0[p0 + 8] = acc[mi][ni][2] + bq0;
            o1[p0 + 8] = acc[mi][ni][3] + bq1;
        }
    }
}

extern "C" void kernel_launch(void* const* d_in, const int* in_sizes, int n_in,
                              void* d_out, int out_size) {
    const float* in   = (const float*)d_in[0];
    const float* w    = (const float*)d_in[1];
    const float* bias = (const float*)d_in[2];
    float* out = (float*)d_out;

    cudaFuncSetAttribute(conv_kernel,
                         cudaFuncAttributeMaxDynamicSharedMemorySize, SMEM_TOTAL);

    wprep_kernel<<<(WFRAG_U32 + 255) / 256, 256>>>(w);
    conv_kernel<<<dim3(14, BATCH), THREADS, SMEM_TOTAL>>>(in, bias, out);
}

// round 11
// speedup vs baseline: 1.6621x; 1.0734x over previous
#include <cuda_runtime.h>
#include <cuda_bf16.h>
#include <cstdint>

// Problem constants
#define BATCH 32
#define CIN   64
#define HH    56
#define WW    56
#define NOUT  128
#define IMG   (HH*WW)          // 3136

// Tiling: CTA = 224 real px (4 rows) padded to 256 px, x 128 n
#define ROWS_PER_CTA 4
#define THREADS 1024
#define IN_LINES (6*58)                 // halo tile lines
#define IN_SM_BYTES (IN_LINES*128)      // 44544 (64ch * 2B per line, 8x16B swizzled chunks)
#define WFRAG_U32 (9*4*8*32*4)          // 36864 u32 = 147456 B
#define WFRAG_BYTES (WFRAG_U32*4)
#define SMEM_TOTAL (IN_SM_BYTES + WFRAG_BYTES)   // 192000

// Weights pre-packed in mma B-fragment order, both n-tiles contiguous per lane:
// [kk][ks][np(8)][lane(32)][4] u32
//   j=0,1 -> n-block nb=np*2   : { W[nb*8+g][ks*16+kq*2], W[..][ks*16+8+kq*2] }
//   j=2,3 -> n-block nb=np*2+1 : same for the next 8 output channels
__device__ uint32_t g_wq[WFRAG_U32];

__global__ void wprep_kernel(const float* __restrict__ w) {
    int idx = blockIdx.x * 256 + threadIdx.x;
    if (idx >= WFRAG_U32) return;
    int j    = idx & 3;
    int lane = (idx >> 2) & 31;
    int np   = (idx >> 7) & 7;
    int ks   = (idx >> 10) & 3;
    int kk   = idx >> 12;
    int g = lane >> 2, kq = lane & 3;
    int nb = np * 2 + (j >> 1);
    int jj = j & 1;
    int n = nb * 8 + g;
    int c = ks * 16 + jj * 8 + kq * 2;
    // gmem weight layout [n][c][kh][kw]; RNE fp32->bf16 == float_quantize(8,7)
    __nv_bfloat16 lo = __float2bfloat16(w[(n * 64 + c) * 9 + kk]);
    __nv_bfloat16 hi = __float2bfloat16(w[(n * 64 + c + 1) * 9 + kk]);
    g_wq[idx] = (uint32_t)(*(const uint16_t*)&lo) |
                ((uint32_t)(*(const uint16_t*)&hi) << 16);
}

__global__ void __launch_bounds__(THREADS, 1)
conv_kernel(const float* __restrict__ in, const float* __restrict__ bias,
            float* __restrict__ out) {
    extern __shared__ char smb[];
    char* insmB = smb;
    char* wsmB  = smb + IN_SM_BYTES;

    const int ty   = blockIdx.x;     // 0..13  (group of 4 output rows)
    const int b    = blockIdx.y;     // 0..31
    const int tid  = threadIdx.x;
    const int lane = tid & 31;
    const int warp = tid >> 5;       // 0..31
    const int y0   = ty * ROWS_PER_CTA;

    // ---- weight fragments: async copy gmem->smem, overlapped with input stage
    {
        uint32_t wdst = (uint32_t)__cvta_generic_to_shared(wsmB);
        const char* wsrc = (const char*)g_wq;
        #pragma unroll 3
        for (int it = 0; it < 9; ++it) {
            int s = it * THREADS + tid;          // 9216 16B chunks
            asm volatile("cp.async.cg.shared.global [%0], [%1], 16;\n"
                         :: "r"(wdst + s * 16), "l"(wsrc + (size_t)s * 16));
        }
        asm volatile("cp.async.commit_group;\n");
    }

    // ---- stage input halo tile (fp32 -> bf16, swizzled) ---------------------
    {
        const float* inb = in + (size_t)b * CIN * IMG;
        #pragma unroll 4
        for (int it = 0; it < 24; ++it) {
            int s  = it * THREADS + tid;   // 0..24575
            int r  = s >> 12;              // 0..5   (halo row, y = y0-1+r)
            int c  = (s >> 6) & 63;        // channel
            int xi = s & 63;               // halo col (x = xi-1), 58..63 unused
            int y  = y0 - 1 + r;
            int x  = xi - 1;
            float v = 0.f;
            if (y >= 0 && y < HH && x >= 0 && x < WW)
                v = inb[c * IMG + y * WW + x];
            if (xi < 58) {
                int line = r * 58 + xi;
                int byte = line * 128 + ((((c >> 3) ^ (line & 7)) << 4) | ((c & 7) * 2));
                *(__nv_bfloat16*)(insmB + byte) = __float2bfloat16(v);
            }
        }
    }
    asm volatile("cp.async.wait_group 0;\n" ::: "memory");
    __syncthreads();

    // ---- warp tiling: 4(M) x 8(N) warps, warp tile 64px x 16n ---------------
    const int warpM = warp & 3;        // 0..3 -> 64 px each (px 224..255 dummy)
    const int warpN = warp >> 2;       // 0..7 -> 16 channels each
    const int g  = lane >> 2;          // 0..7
    const int kq = lane & 3;           // 0..3
    const int rl = lane & 15;          // ldmatrix row within 16-row A tile
    const int hi16 = ((lane >> 4) & 1) << 4;   // k-half select for ldmatrix ptr

    const uint32_t insm32 = (uint32_t)__cvta_generic_to_shared(insmB);
    const uint32_t* wfr = (const uint32_t*)wsmB;

    // per-lane halo-line base for each of the 4 m16 tiles (dummy px remapped)
    int lineBase[4];
    #pragma unroll
    for (int mi = 0; mi < 4; ++mi) {
        int p = warpM * 64 + mi * 16 + rl;
        if (p >= 224) p -= 224;        // dummy tiles read valid (discarded) data
        lineBase[mi] = (p / 56) * 58 + (p % 56);
    }

    float acc[4][2][4];
    #pragma unroll
    for (int mi = 0; mi < 4; ++mi)
        #pragma unroll
        for (int ni = 0; ni < 2; ++ni)
            #pragma unroll
            for (int q = 0; q < 4; ++q) acc[mi][ni][q] = 0.f;

    // ---- main loop: 9 (kh,kw) x 4 k16-steps --------------------------------
    int kh = 0, kw = 0;
    #pragma unroll 1
    for (int kk = 0; kk < 9; ++kk) {
        const int lineOff = kh * 58 + kw;

        uint32_t base[4], X7[4];
        #pragma unroll
        for (int mi = 0; mi < 4; ++mi) {
            int l = lineBase[mi] + lineOff;
            base[mi] = insm32 + l * 128;
            X7[mi]   = (l & 7) << 4;
        }

        #pragma unroll
        for (int ks = 0; ks < 4; ++ks) {
            // B fragments: single conflict-free LDS.128 covers both n-tiles
            uint4 B = *(const uint4*)(wfr + ((((kk * 4 + ks) * 8 + warpN) * 32 + lane) << 2));

            const uint32_t off = (uint32_t)(ks * 32 + hi16);
            #pragma unroll
            for (int mi = 0; mi < 4; ++mi) {
                uint32_t a0, a1, a2, a3;
                uint32_t addr = base[mi] + (off ^ X7[mi]);
                asm volatile(
                    "ldmatrix.sync.aligned.m8n8.x4.shared.b16 {%0,%1,%2,%3}, [%4];\n"
                    : "=r"(a0), "=r"(a1), "=r"(a2), "=r"(a3) : "r"(addr));
                asm volatile(
                    "mma.sync.aligned.m16n8k16.row.col.f32.bf16.bf16.f32 "
                    "{%0,%1,%2,%3}, {%4,%5,%6,%7}, {%8,%9}, {%0,%1,%2,%3};\n"
                    : "+f"(acc[mi][0][0]), "+f"(acc[mi][0][1]),
                      "+f"(acc[mi][0][2]), "+f"(acc[mi][0][3])
                    : "r"(a0), "r"(a1), "r"(a2), "r"(a3),
                      "r"(B.x), "r"(B.y));
                asm volatile(
                    "mma.sync.aligned.m16n8k16.row.col.f32.bf16.bf16.f32 "
                    "{%0,%1,%2,%3}, {%4,%5,%6,%7}, {%8,%9}, {%0,%1,%2,%3};\n"
                    : "+f"(acc[mi][1][0]), "+f"(acc[mi][1][1]),
                      "+f"(acc[mi][1][2]), "+f"(acc[mi][1][3])
                    : "r"(a0), "r"(a1), "r"(a2), "r"(a3),
                      "r"(B.z), "r"(B.w));
            }
        }
        if (++kw == 3) { kw = 0; ++kh; }
    }

    // ---- epilogue: + bf16(bias), NCHW store (skip dummy tiles) -------------
    float* outb = out + (size_t)b * NOUT * IMG + ty * 224;
    #pragma unroll
    for (int ni = 0; ni < 2; ++ni) {
        int n0 = warpN * 16 + ni * 8 + kq * 2;
        float bq0 = __bfloat162float(__float2bfloat16(__ldg(bias + n0)));
        float bq1 = __bfloat162float(__float2bfloat16(__ldg(bias + n0 + 1)));
        float* o0 = outb + (size_t)n0 * IMG;
        float* o1 = o0 + IMG;
        #pragma unroll
        for (int mi = 0; mi < 4; ++mi) {
            int pt = warpM * 64 + mi * 16;
            if (pt >= 224) continue;           // dummy tile
            int p0 = pt + g;
            o0[p0]     = acc[mi][ni][0] + bq0;
            o1[p0]     = acc[mi][ni][1] + bq1;
            o0[p0 + 8] = acc[mi][ni][2] + bq0;
            o1[p0 + 8] = acc[mi][ni][3] + bq1;
        }
    }
}

extern "C" void kernel_launch(void* const* d_in, const int* in_sizes, int n_in,
                              void* d_out, int out_size) {
    const float* in   = (const float*)d_in[0];
    const float* w    = (const float*)d_in[1];
    const float* bias = (const float*)d_in[2];
    float* out = (float*)d_out;

    cudaFuncSetAttribute(conv_kernel,
                         cudaFuncAttributeMaxDynamicSharedMemorySize, SMEM_TOTAL);

    wprep_kernel<<<(WFRAG_U32 + 255) / 256, 256>>>(w);
    conv_kernel<<<dim3(14, BATCH), THREADS, SMEM_TOTAL>>>(in, bias, out);
}

// round 13
// speedup vs baseline: 1.9431x; 1.1690x over previous
#include <cuda_runtime.h>
#include <cuda_bf16.h>
#include <cstdint>

// Problem constants
#define BATCH 32
#define CIN   64
#define HH    56
#define WW    56
#define NOUT  128
#define IMG   (HH*WW)          // 3136

// Tiling: CTA = 224 px (4 rows x 56) x 128 n, 28 warps as 7(M) x 4(N), warp 32x32
#define ROWS_PER_CTA 4
#define THREADS 896
#define IN_LINES (6*58)                 // halo tile lines
#define IN_SM_BYTES (IN_LINES*128)      // 44544 (64ch * 2B per line, 8x16B swizzled chunks)
#define WFRAG_U32 (9*4*8*32*4)          // 36864 u32 = 147456 B
#define WFRAG_BYTES (WFRAG_U32*4)
#define SMEM_TOTAL (IN_SM_BYTES + WFRAG_BYTES)   // 192000

// Weights pre-packed in mma B-fragment order, two n8-tiles contiguous per lane:
// [kk][ks][np(8)][lane(32)][4] u32
//   j=0,1 -> n = np*16 + g     : { W[n][ks*16+kq*2], W[n][ks*16+8+kq*2] }
//   j=2,3 -> n = np*16 + 8 + g : same
__device__ uint32_t g_wq[WFRAG_U32];

__global__ void wprep_kernel(const float* __restrict__ w) {
    int idx = blockIdx.x * 256 + threadIdx.x;
    if (idx >= WFRAG_U32) return;
    int j    = idx & 3;
    int lane = (idx >> 2) & 31;
    int np   = (idx >> 7) & 7;
    int ks   = (idx >> 10) & 3;
    int kk   = idx >> 12;
    int g = lane >> 2, kq = lane & 3;
    int n = np * 16 + (j >> 1) * 8 + g;
    int c = ks * 16 + (j & 1) * 8 + kq * 2;
    // gmem weight layout [n][c][kh][kw]; RNE fp32->bf16 == float_quantize(8,7)
    __nv_bfloat16 lo = __float2bfloat16(w[(n * 64 + c) * 9 + kk]);
    __nv_bfloat16 hi = __float2bfloat16(w[(n * 64 + c + 1) * 9 + kk]);
    g_wq[idx] = (uint32_t)(*(const uint16_t*)&lo) |
                ((uint32_t)(*(const uint16_t*)&hi) << 16);
}

__global__ void __launch_bounds__(THREADS, 1)
conv_kernel(const float* __restrict__ in, const float* __restrict__ bias,
            float* __restrict__ out) {
    extern __shared__ char smb[];
    char* insmB = smb;
    char* wsmB  = smb + IN_SM_BYTES;

    const int ty   = blockIdx.x;     // 0..13  (group of 4 output rows)
    const int b    = blockIdx.y;     // 0..31
    const int tid  = threadIdx.x;
    const int lane = tid & 31;
    const int warp = tid >> 5;       // 0..27
    const int y0   = ty * ROWS_PER_CTA;

    // ---- weight fragments: async copy gmem->smem, overlapped with input stage
    {
        uint32_t wdst = (uint32_t)__cvta_generic_to_shared(wsmB);
        const char* wsrc = (const char*)g_wq;
        #pragma unroll
        for (int it = 0; it < 11; ++it) {
            int s = it * THREADS + tid;          // 9216 16B chunks
            if (s < WFRAG_BYTES / 16)
                asm volatile("cp.async.cg.shared.global [%0], [%1], 16;\n"
                             :: "r"(wdst + s * 16), "l"(wsrc + (size_t)s * 16));
        }
        asm volatile("cp.async.commit_group;\n");
    }

    // ---- stage input halo tile (fp32 -> bf16, swizzled) ---------------------
    {
        const float* inb = in + (size_t)b * CIN * IMG;
        #pragma unroll 4
        for (int it = 0; it < 28; ++it) {
            int s  = it * THREADS + tid;   // 0..24575
            if (s < 24576) {
                int r  = s >> 12;              // 0..5   (halo row, y = y0-1+r)
                int c  = (s >> 6) & 63;        // channel
                int xi = s & 63;               // halo col (x = xi-1), 58..63 unused
                int y  = y0 - 1 + r;
                int x  = xi - 1;
                float v = 0.f;
                if (y >= 0 && y < HH && x >= 0 && x < WW)
                    v = inb[c * IMG + y * WW + x];
                if (xi < 58) {
                    int line = r * 58 + xi;
                    int byte = line * 128 + ((((c >> 3) ^ (line & 7)) << 4) | ((c & 7) * 2));
                    *(__nv_bfloat16*)(insmB + byte) = __float2bfloat16(v);
                }
            }
        }
    }

    // ---- warp tiling: 7(M) x 4(N), warp tile 32px x 32n ---------------------
    const int warpN = warp & 3;        // 0..3 -> 32 channels each
    const int warpM = warp >> 2;       // 0..6 -> 32 px each (all real)
    const int g  = lane >> 2;          // 0..7
    const int kq = lane & 3;           // 0..3
    const int rl = lane & 15;          // ldmatrix row within 16-row A tile
    const int hi16 = ((lane >> 4) & 1) << 4;   // k-half select for ldmatrix ptr

    const uint32_t insm32 = (uint32_t)__cvta_generic_to_shared(insmB);
    // per-(kk,ks) B block base for this warp/lane: [kk*4+ks][np][lane][4] u32
    const uint32_t* wfrW = (const uint32_t*)wsmB + ((warpN * 2) * 32 + lane) * 4;

    // bias (bf16-quantized) hoisted: n0 = warpN*32 + ni*8 + kq*2
    float bq[4][2];
    #pragma unroll
    for (int ni = 0; ni < 4; ++ni) {
        int n0 = warpN * 32 + ni * 8 + kq * 2;
        bq[ni][0] = __bfloat162float(__float2bfloat16(__ldg(bias + n0)));
        bq[ni][1] = __bfloat162float(__float2bfloat16(__ldg(bias + n0 + 1)));
    }

    // per-lane halo-line base for each of the 2 m16 tiles
    int lineBase[2];
    #pragma unroll
    for (int mi = 0; mi < 2; ++mi) {
        int p = warpM * 32 + mi * 16 + rl;
        lineBase[mi] = (p / 56) * 58 + (p % 56);
    }

    float acc[2][4][4];
    #pragma unroll
    for (int mi = 0; mi < 2; ++mi)
        #pragma unroll
        for (int ni = 0; ni < 4; ++ni)
            #pragma unroll
            for (int q = 0; q < 4; ++q) acc[mi][ni][q] = 0.f;

    asm volatile("cp.async.wait_group 0;\n" ::: "memory");
    __syncthreads();

    // ---- main loop: 9 (kh,kw) x 4 k16-steps --------------------------------
    int kh = 0, kw = 0;
    #pragma unroll 1
    for (int kk = 0; kk < 9; ++kk) {
        const int lineOff = kh * 58 + kw;

        uint32_t base[2], X7[2];
        #pragma unroll
        for (int mi = 0; mi < 2; ++mi) {
            int l = lineBase[mi] + lineOff;
            base[mi] = insm32 + l * 128;
            X7[mi]   = (l & 7) << 4;
        }

        #pragma unroll
        for (int ks = 0; ks < 4; ++ks) {
            // B fragments: two conflict-free LDS.128 cover the 32-n warp tile
            const uint32_t* bp = wfrW + (kk * 4 + ks) * 1024;
            uint4 B0 = *(const uint4*)bp;            // n [warpN*32,    +16)
            uint4 B1 = *(const uint4*)(bp + 128);    // n [warpN*32+16, +16)

            const uint32_t off = (uint32_t)(ks * 32 + hi16);
            uint32_t a[2][4];
            #pragma unroll
            for (int mi = 0; mi < 2; ++mi) {
                uint32_t addr = base[mi] + (off ^ X7[mi]);
                asm volatile(
                    "ldmatrix.sync.aligned.m8n8.x4.shared.b16 {%0,%1,%2,%3}, [%4];\n"
                    : "=r"(a[mi][0]), "=r"(a[mi][1]), "=r"(a[mi][2]), "=r"(a[mi][3])
                    : "r"(addr));
            }
            #pragma unroll
            for (int mi = 0; mi < 2; ++mi) {
                #define MMA(NI, BX, BY)                                          \
                    asm volatile(                                                \
                        "mma.sync.aligned.m16n8k16.row.col.f32.bf16.bf16.f32 "   \
                        "{%0,%1,%2,%3}, {%4,%5,%6,%7}, {%8,%9}, {%0,%1,%2,%3};\n"\
                        : "+f"(acc[mi][NI][0]), "+f"(acc[mi][NI][1]),            \
                          "+f"(acc[mi][NI][2]), "+f"(acc[mi][NI][3])             \
                        : "r"(a[mi][0]), "r"(a[mi][1]), "r"(a[mi][2]),           \
                          "r"(a[mi][3]), "r"(BX), "r"(BY))
                MMA(0, B0.x, B0.y);
                MMA(1, B0.z, B0.w);
                MMA(2, B1.x, B1.y);
                MMA(3, B1.z, B1.w);
                #undef MMA
            }
        }
        if (++kw == 3) { kw = 0; ++kh; }
    }

    // ---- epilogue: + bf16(bias), NCHW store --------------------------------
    float* outb = out + (size_t)b * NOUT * IMG + ty * 224;
    #pragma unroll
    for (int ni = 0; ni < 4; ++ni) {
        int n0 = warpN * 32 + ni * 8 + kq * 2;
        float* o0 = outb + (size_t)n0 * IMG;
        float* o1 = o0 + IMG;
        #pragma unroll
        for (int mi = 0; mi < 2; ++mi) {
            int p0 = warpM * 32 + mi * 16 + g;
            o0[p0]     = acc[mi][ni][0] + bq[ni][0];
            o1[p0]     = acc[mi][ni][1] + bq[ni][1];
            o0[p0 + 8] = acc[mi][ni][2] + bq[ni][0];
            o1[p0 + 8] = acc[mi][ni][3] + bq[ni][1];
        }
    }
}

extern "C" void kernel_launch(void* const* d_in, const int* in_sizes, int n_in,
                              void* d_out, int out_size) {
    const float* in   = (const float*)d_in[0];
    const float* w    = (const float*)d_in[1];
    const float* bias = (const float*)d_in[2];
    float* out = (float*)d_out;

    cudaFuncSetAttribute(conv_kernel,
                         cudaFuncAttributeMaxDynamicSharedMemorySize, SMEM_TOTAL);

    wprep_kernel<<<(WFRAG_U32 + 255) / 256, 256>>>(w);
    conv_kernel<<<dim3(14, BATCH), THREADS, SMEM_TOTAL>>>(in, bias, out);
}

// round 14
// speedup vs baseline: 1.9614x; 1.0094x over previous
#include <cuda_runtime.h>
#include <cuda_bf16.h>
#include <cstdint>

// Problem constants
#define BATCH 32
#define CIN   64
#define HH    56
#define WW    56
#define NOUT  128
#define IMG   (HH*WW)          // 3136

// Tiling: CTA = 224 px (4 rows x 56) x 128 n, 28 warps as 7(M) x 4(N), warp 32x32
#define ROWS_PER_CTA 4
#define THREADS 896
#define IN_LINES (6*58)                 // halo tile lines
#define IN_SM_BYTES (IN_LINES*128)      // 44544 (64ch * 2B per line, 8x16B swizzled chunks)
#define WFRAG_U32 (9*4*8*32*4)          // 36864 u32 = 147456 B
#define WFRAG_BYTES (WFRAG_U32*4)
#define SMEM_TOTAL (IN_SM_BYTES + WFRAG_BYTES)   // 192000

// Weights pre-packed in mma B-fragment order, two n8-tiles contiguous per lane:
// [kk][ks][np(8)][lane(32)][4] u32
//   j=0,1 -> n = np*16 + g     : { W[n][ks*16+kq*2], W[n][ks*16+8+kq*2] }
//   j=2,3 -> n = np*16 + 8 + g : same
__device__ uint32_t g_wq[WFRAG_U32];

__global__ void wprep_kernel(const float* __restrict__ w) {
    int idx = blockIdx.x * 256 + threadIdx.x;
    if (idx >= WFRAG_U32) return;
    int j    = idx & 3;
    int lane = (idx >> 2) & 31;
    int np   = (idx >> 7) & 7;
    int ks   = (idx >> 10) & 3;
    int kk   = idx >> 12;
    int g = lane >> 2, kq = lane & 3;
    int n = np * 16 + (j >> 1) * 8 + g;
    int c = ks * 16 + (j & 1) * 8 + kq * 2;
    // gmem weight layout [n][c][kh][kw]; RNE fp32->bf16 == float_quantize(8,7)
    __nv_bfloat16 lo = __float2bfloat16(w[(n * 64 + c) * 9 + kk]);
    __nv_bfloat16 hi = __float2bfloat16(w[(n * 64 + c + 1) * 9 + kk]);
    g_wq[idx] = (uint32_t)(*(const uint16_t*)&lo) |
                ((uint32_t)(*(const uint16_t*)&hi) << 16);
}

__global__ void __launch_bounds__(THREADS, 1)
conv_kernel(const float* __restrict__ in, const float* __restrict__ bias,
            float* __restrict__ out) {
    extern __shared__ char smb[];
    char* insmB = smb;
    char* wsmB  = smb + IN_SM_BYTES;

    const int ty   = blockIdx.x;     // 0..13  (group of 4 output rows)
    const int b    = blockIdx.y;     // 0..31
    const int tid  = threadIdx.x;
    const int lane = tid & 31;
    const int warp = tid >> 5;       // 0..27
    const int y0   = ty * ROWS_PER_CTA;

    // ---- weight fragments: async copy gmem->smem, overlapped with input stage
    {
        uint32_t wdst = (uint32_t)__cvta_generic_to_shared(wsmB);
        const char* wsrc = (const char*)g_wq;
        #pragma unroll
        for (int it = 0; it < 11; ++it) {
            int s = it * THREADS + tid;          // 9216 16B chunks
            if (s < WFRAG_BYTES / 16)
                asm volatile("cp.async.cg.shared.global [%0], [%1], 16;\n"
                             :: "r"(wdst + s * 16), "l"(wsrc + (size_t)s * 16));
        }
        asm volatile("cp.async.commit_group;\n");
    }

    // ---- stage input halo tile (fp32 -> bf16, swizzled) ---------------------
    {
        const float* inb = in + (size_t)b * CIN * IMG;
        #pragma unroll 4
        for (int it = 0; it < 28; ++it) {
            int s  = it * THREADS + tid;   // 0..24575
            if (s < 24576) {
                int r  = s >> 12;              // 0..5   (halo row, y = y0-1+r)
                int c  = (s >> 6) & 63;        // channel
                int xi = s & 63;               // halo col (x = xi-1), 58..63 unused
                int y  = y0 - 1 + r;
                int x  = xi - 1;
                float v = 0.f;
                if (y >= 0 && y < HH && x >= 0 && x < WW)
                    v = inb[c * IMG + y * WW + x];
                if (xi < 58) {
                    int line = r * 58 + xi;
                    int byte = line * 128 + ((((c >> 3) ^ (line & 7)) << 4) | ((c & 7) * 2));
                    *(__nv_bfloat16*)(insmB + byte) = __float2bfloat16(v);
                }
            }
        }
    }

    // ---- warp tiling: 7(M) x 4(N), warp tile 32px x 32n ---------------------
    const int warpN = warp & 3;        // 0..3 -> 32 channels each
    const int warpM = warp >> 2;       // 0..6 -> 32 px each (all real)
    const int g  = lane >> 2;          // 0..7
    const int kq = lane & 3;           // 0..3
    const int rl = lane & 15;          // ldmatrix row within 16-row A tile
    const int hi16 = ((lane >> 4) & 1) << 4;   // k-half select for ldmatrix ptr

    const uint32_t insm32 = (uint32_t)__cvta_generic_to_shared(insmB);
    // per-(kk,ks) B block base for this warp/lane: [kk*4+ks][np][lane][4] u32
    const uint32_t* wfrW = (const uint32_t*)wsmB + ((warpN * 2) * 32 + lane) * 4;

    // bias (bf16-quantized) hoisted: n0 = warpN*32 + ni*8 + kq*2
    float bq[4][2];
    #pragma unroll
    for (int ni = 0; ni < 4; ++ni) {
        int n0 = warpN * 32 + ni * 8 + kq * 2;
        bq[ni][0] = __bfloat162float(__float2bfloat16(__ldg(bias + n0)));
        bq[ni][1] = __bfloat162float(__float2bfloat16(__ldg(bias + n0 + 1)));
    }

    // per-lane halo-line base for each of the 2 m16 tiles
    int lineBase[2];
    #pragma unroll
    for (int mi = 0; mi < 2; ++mi) {
        int p = warpM * 32 + mi * 16 + rl;
        lineBase[mi] = (p / 56) * 58 + (p % 56);
    }

    float acc[2][4][4];
    #pragma unroll
    for (int mi = 0; mi < 2; ++mi)
        #pragma unroll
        for (int ni = 0; ni < 4; ++ni)
            #pragma unroll
            for (int q = 0; q < 4; ++q) acc[mi][ni][q] = 0.f;

    asm volatile("cp.async.wait_group 0;\n" ::: "memory");
    __syncthreads();

    // ---- main loop: 3 kernel rows x (3 kw x 4 k16-steps) --------------------
    // NOTE: ldmatrix / mma are NON-volatile so the compiler can software-
    // pipeline loads of step s+1 into the MMA chain of step s.
    #pragma unroll 1
    for (int kh = 0; kh < 3; ++kh) {
        const int rowOff = kh * 58;
        #pragma unroll
        for (int kw = 0; kw < 3; ++kw) {
            const int lineOff = rowOff + kw;
            const int kkBase  = (kh * 3 + kw) * 4;

            uint32_t base[2], X7[2];
            #pragma unroll
            for (int mi = 0; mi < 2; ++mi) {
                int l = lineBase[mi] + lineOff;
                base[mi] = insm32 + l * 128;
                X7[mi]   = (l & 7) << 4;
            }

            #pragma unroll
            for (int ks = 0; ks < 4; ++ks) {
                // B fragments: two conflict-free LDS.128 cover the 32-n warp tile
                const uint32_t* bp = wfrW + (kkBase + ks) * 1024;
                uint4 B0 = *(const uint4*)bp;            // n [warpN*32,    +16)
                uint4 B1 = *(const uint4*)(bp + 128);    // n [warpN*32+16, +16)

                const uint32_t off = (uint32_t)(ks * 32 + hi16);
                uint32_t a[2][4];
                #pragma unroll
                for (int mi = 0; mi < 2; ++mi) {
                    uint32_t addr = base[mi] + (off ^ X7[mi]);
                    asm("ldmatrix.sync.aligned.m8n8.x4.shared.b16 {%0,%1,%2,%3}, [%4];\n"
                        : "=r"(a[mi][0]), "=r"(a[mi][1]), "=r"(a[mi][2]), "=r"(a[mi][3])
                        : "r"(addr));
                }
                #pragma unroll
                for (int mi = 0; mi < 2; ++mi) {
                    #define MMA(NI, BX, BY)                                          \
                        asm("mma.sync.aligned.m16n8k16.row.col.f32.bf16.bf16.f32 "   \
                            "{%0,%1,%2,%3}, {%4,%5,%6,%7}, {%8,%9}, {%0,%1,%2,%3};\n"\
                            : "+f"(acc[mi][NI][0]), "+f"(acc[mi][NI][1]),            \
                              "+f"(acc[mi][NI][2]), "+f"(acc[mi][NI][3])             \
                            : "r"(a[mi][0]), "r"(a[mi][1]), "r"(a[mi][2]),           \
                              "r"(a[mi][3]), "r"(BX), "r"(BY))
                    MMA(0, B0.x, B0.y);
                    MMA(1, B0.z, B0.w);
                    MMA(2, B1.x, B1.y);
                    MMA(3, B1.z, B1.w);
                    #undef MMA
                }
            }
        }
    }

    // ---- epilogue: + bf16(bias), NCHW store --------------------------------
    float* outb = out + (size_t)b * NOUT * IMG + ty * 224;
    #pragma unroll
    for (int ni = 0; ni < 4; ++ni) {
        int n0 = warpN * 32 + ni * 8 + kq * 2;
        float* o0 = outb + (size_t)n0 * IMG;
        float* o1 = o0 + IMG;
        #pragma unroll
        for (int mi = 0; mi < 2; ++mi) {
            int p0 = warpM * 32 + mi * 16 + g;
            o0[p0]     = acc[mi][ni][0] + bq[ni][0];
            o1[p0]     = acc[mi][ni][1] + bq[ni][1];
            o0[p0 + 8] = acc[mi][ni][2] + bq[ni][0];
            o1[p0 + 8] = acc[mi][ni][3] + bq[ni][1];
        }
    }
}

extern "C" void kernel_launch(void* const* d_in, const int* in_sizes, int n_in,
                              void* d_out, int out_size) {
    const float* in   = (const float*)d_in[0];
    const float* w    = (const float*)d_in[1];
    const float* bias = (const float*)d_in[2];
    float* out = (float*)d_out;

    cudaFuncSetAttribute(conv_kernel,
                         cudaFuncAttributeMaxDynamicSharedMemorySize, SMEM_TOTAL);

    wprep_kernel<<<(WFRAG_U32 + 255) / 256, 256>>>(w);
    conv_kernel<<<dim3(14, BATCH), THREADS, SMEM_TOTAL>>>(in, bias, out);
}